// round 10
// baseline (speedup 1.0000x reference)
#include <cuda_runtime.h>
#include <cuda_bf16.h>
#include <math.h>
#include <stdint.h>

#define N_NODES 30000
#define N_REL   38
#define N_EDGE  200000
#define HID     64
#define PAD     68     // fp32 stage row stride
#define ASTR    72     // bf16 smem tile row stride (144B: conflict-free frags)
#define N_CHUNK 5

// ---------------- scratch ----------------
__device__ float g_H  [(size_t)N_REL * N_NODES * HID];
__device__ float g_OUT[(size_t)N_REL * N_NODES * HID];
__device__ float g_Ssrc[N_REL * N_NODES];
__device__ float g_Sdst[N_REL * N_NODES];
__device__ float g_DEN [N_REL * N_NODES];
__device__ float g_PREP[N_CHUNK][(size_t)N_NODES * HID];
__device__ int   g_cnt [N_REL * N_NODES];      // counts -> cursor -> row end
__device__ int   g_off [N_REL * N_NODES];      // row start
__device__ int2  g_epk [(size_t)N_REL * N_EDGE]; // (src, w) sorted by dst
__device__ __align__(16) __nv_bfloat16 g_EH [(size_t)N_NODES * HID];
__device__ __align__(16) __nv_bfloat16 g_EL [(size_t)N_NODES * HID];
__device__ __align__(16) __nv_bfloat16 g_WH [(size_t)N_REL * 4096];
__device__ __align__(16) __nv_bfloat16 g_WL [(size_t)N_REL * 4096];
__device__ __align__(16) __nv_bfloat16 g_W1H[(size_t)(N_REL + 1) * 4096];
__device__ __align__(16) __nv_bfloat16 g_W1L[(size_t)(N_REL + 1) * 4096];
__device__ __align__(16) __nv_bfloat16 g_W2H[4096];
__device__ __align__(16) __nv_bfloat16 g_W2L[4096];

__device__ __forceinline__ float lrelu(float x) { return x > 0.f ? x : 0.2f * x; }
__device__ __forceinline__ void split1(float x, __nv_bfloat16& h, __nv_bfloat16& l) {
    h = __float2bfloat16(x);
    l = __float2bfloat16(x - __bfloat162float(h));
}
__device__ __forceinline__ uint32_t pk(__nv_bfloat16 a, __nv_bfloat16 b) {
    __nv_bfloat162 v; v.x = a; v.y = b;
    return *(uint32_t*)&v;
}

// ---------------- mma.sync m16n8k16 bf16 ----------------
__device__ __forceinline__ void mma16816(float* d, const uint32_t* a, uint32_t b0, uint32_t b1) {
    asm volatile(
        "mma.sync.aligned.m16n8k16.row.col.f32.bf16.bf16.f32 "
        "{%0,%1,%2,%3}, {%4,%5,%6,%7}, {%8,%9}, {%0,%1,%2,%3};"
        : "+f"(d[0]), "+f"(d[1]), "+f"(d[2]), "+f"(d[3])
        : "r"(a[0]), "r"(a[1]), "r"(a[2]), "r"(a[3]), "r"(b0), "r"(b1));
}
__device__ __forceinline__ void lda_frag(uint32_t* a, const __nv_bfloat16* T,
                                         int wr, int j0, int g, int t) {
    a[0] = *(const uint32_t*)&T[(wr + g)     * ASTR + j0 + 2 * t];
    a[1] = *(const uint32_t*)&T[(wr + g + 8) * ASTR + j0 + 2 * t];
    a[2] = *(const uint32_t*)&T[(wr + g)     * ASTR + j0 + 2 * t + 8];
    a[3] = *(const uint32_t*)&T[(wr + g + 8) * ASTR + j0 + 2 * t + 8];
}
__device__ __forceinline__ void warp_mma_3term(
    const __nv_bfloat16* Ah, const __nv_bfloat16* Al,
    const __nv_bfloat16* Bh, const __nv_bfloat16* Bl,
    int wr, int g, int t, float acc[8][4])
{
#pragma unroll
    for (int kc = 0; kc < 4; ++kc) {
        const int j0 = kc * 16;
        uint32_t ah[4], al[4];
        lda_frag(ah, Ah, wr, j0, g, t);
        lda_frag(al, Al, wr, j0, g, t);
#pragma unroll
        for (int nt = 0; nt < 8; ++nt) {
            const int c = nt * 8 + g;
            uint32_t bh0 = *(const uint32_t*)&Bh[c * ASTR + j0 + 2 * t];
            uint32_t bh1 = *(const uint32_t*)&Bh[c * ASTR + j0 + 2 * t + 8];
            uint32_t bl0 = *(const uint32_t*)&Bl[c * ASTR + j0 + 2 * t];
            uint32_t bl1 = *(const uint32_t*)&Bl[c * ASTR + j0 + 2 * t + 8];
            mma16816(acc[nt], ah, bh0, bh1);
            mma16816(acc[nt], al, bh0, bh1);
            mma16816(acc[nt], ah, bl0, bl1);
        }
    }
}
__device__ __forceinline__ void acc_to_stage(float* stage, const float acc[8][4],
                                             int wr, int g, int t) {
#pragma unroll
    for (int nt = 0; nt < 8; ++nt) {
        *(float2*)&stage[(wr + g)     * PAD + nt * 8 + 2 * t] = make_float2(acc[nt][0], acc[nt][1]);
        *(float2*)&stage[(wr + g + 8) * PAD + nt * 8 + 2 * t] = make_float2(acc[nt][2], acc[nt][3]);
    }
}

// ---------------- prep kernels ----------------
__global__ void prep_emb(const float* __restrict__ emb) {
    int i = blockIdx.x * 256 + threadIdx.x;
    if (i < N_NODES * HID / 2) {
        float2 v = ((const float2*)emb)[i];
        __nv_bfloat16 h0, l0, h1, l1;
        split1(v.x, h0, l0); split1(v.y, h1, l1);
        ((uint32_t*)g_EH)[i] = pk(h0, h1);
        ((uint32_t*)g_EL)[i] = pk(l0, l1);
    }
}
__global__ void prep_w(const float* __restrict__ W) {
    int i = blockIdx.x * 256 + threadIdx.x;
    if (i < N_REL * 4096) {
        int rel = i >> 12, r = i & 4095, c = r >> 6, j = r & 63;
        split1(W[(rel << 12) + (j << 6) + c], g_WH[i], g_WL[i]);
    }
}
__global__ void prep_w1(const float* __restrict__ W1) {
    int i = blockIdx.x * 256 + threadIdx.x;
    if (i < (N_REL + 1) * 4096) {
        int seg = i >> 12, r = i & 4095, c = r >> 6, j = r & 63;
        split1(W1[((size_t)seg * 64 + j) * 64 + c], g_W1H[i], g_W1L[i]);
    }
}
__global__ void prep_w2(const float* __restrict__ W2) {
    int i = blockIdx.x * 256 + threadIdx.x;
    if (i < 4096) {
        int c = i >> 6, j = i & 63;
        split1(W2[(j << 6) + c], g_W2H[i], g_W2L[i]);
    }
}

// ---------------- CSR build ----------------
__global__ void csr_zero() {
    int i = blockIdx.x * 256 + threadIdx.x;
    if (i < N_REL * N_NODES) g_cnt[i] = 0;
}
__global__ void csr_count(const int* __restrict__ edges) {
    const int rel  = blockIdx.y;
    const int edge = blockIdx.x * 256 + threadIdx.x;
    if (edge < N_EDGE) {
        int d = __ldg(&edges[(size_t)rel * 2 * N_EDGE + N_EDGE + edge]);
        atomicAdd(&g_cnt[rel * N_NODES + d], 1);
    }
}
// per-rel exclusive scan (block 1024); cursor (g_cnt) initialized to start
__global__ __launch_bounds__(1024) void csr_scan() {
    const int rel = blockIdx.x;
    const int tid = threadIdx.x, lane = tid & 31, wid = tid >> 5;
    __shared__ int wtot[32];
    __shared__ int carry;
    if (tid == 0) carry = 0;
    __syncthreads();
    for (int base = 0; base < N_NODES; base += 1024) {
        int idx = base + tid;
        int v = (idx < N_NODES) ? g_cnt[rel * N_NODES + idx] : 0;
        int s = v;
#pragma unroll
        for (int o = 1; o < 32; o <<= 1) {
            int t = __shfl_up_sync(0xffffffffu, s, o);
            if (lane >= o) s += t;
        }
        if (lane == 31) wtot[wid] = s;
        __syncthreads();
        if (wid == 0) {
            int w = wtot[lane];
#pragma unroll
            for (int o = 1; o < 32; o <<= 1) {
                int t = __shfl_up_sync(0xffffffffu, w, o);
                if (lane >= o) w += t;
            }
            wtot[lane] = w;
        }
        __syncthreads();
        int wpre = (wid > 0) ? wtot[wid - 1] : 0;
        int excl = carry + wpre + (s - v);
        if (idx < N_NODES) {
            g_off[rel * N_NODES + idx] = excl;
            g_cnt[rel * N_NODES + idx] = excl;   // cursor = start
        }
        __syncthreads();
        if (tid == 0) carry += wtot[31];
        __syncthreads();
    }
}
__global__ void csr_fill(const int* __restrict__ edges) {
    const int rel  = blockIdx.y;
    const int edge = blockIdx.x * 256 + threadIdx.x;
    if (edge < N_EDGE) {
        const int* eb = edges + (size_t)rel * 2 * N_EDGE;
        int s = __ldg(&eb[edge]);
        int d = __ldg(&eb[N_EDGE + edge]);
        float w = __expf(lrelu(__ldg(&g_Ssrc[rel * N_NODES + s]) +
                               __ldg(&g_Sdst[rel * N_NODES + d])));
        int pos = atomicAdd(&g_cnt[rel * N_NODES + d], 1);
        g_epk[(size_t)rel * N_EDGE + pos] = make_int2(s, __float_as_int(w));
    }
}

// ---------------- gather: OUT[n] = wself*H[n] + Σ w*H[src]; DEN[n] = wself + Σ w ----------------
// 16 lanes per dst node, 16 nodes per block
__global__ __launch_bounds__(256) void gather_kernel() {
    const int rel = blockIdx.y;
    const int n   = blockIdx.x * 16 + (threadIdx.x >> 4);
    const int ql  = threadIdx.x & 15;
    if (n >= N_NODES) return;

    const int start = __ldg(&g_off[rel * N_NODES + n]);
    const int end   = __ldg(&g_cnt[rel * N_NODES + n]);   // cursor after fill = end
    const float wself = __ldg(&g_DEN[rel * N_NODES + n]);

    const float* Hrel = g_H + (size_t)rel * N_NODES * HID;
    float4 h = *(const float4*)&Hrel[(size_t)n * 64 + ql * 4];
    float4 acc = make_float4(wself * h.x, wself * h.y, wself * h.z, wself * h.w);
    float den = wself;

    const int2* ep = g_epk + (size_t)rel * N_EDGE;
    for (int p = start; p < end; ++p) {
        int2 e = __ldg(&ep[p]);
        float w = __int_as_float(e.y);
        float4 hv = *(const float4*)&Hrel[(size_t)e.x * 64 + ql * 4];
        acc.x += w * hv.x; acc.y += w * hv.y;
        acc.z += w * hv.z; acc.w += w * hv.w;
        den += w;
    }

    *(float4*)&g_OUT[((size_t)rel * N_NODES + n) * 64 + ql * 4] = acc;
    if (ql == 0) g_DEN[rel * N_NODES + n] = den;
}

// ---------------- gemm: H = emb @ W[r] + scores (+ DEN seed = wself) ----------------
__global__ __launch_bounds__(256) void gemm_mma(
    const float* __restrict__ att_src, const float* __restrict__ att_dst)
{
    extern __shared__ char sm[];
    __nv_bfloat16* Ah = (__nv_bfloat16*)sm;
    __nv_bfloat16* Al = Ah + 128 * ASTR;
    __nv_bfloat16* Bh = Al + 128 * ASTR;
    __nv_bfloat16* Bl = Bh + 64 * ASTR;
    float* stage = (float*)sm;
    __shared__ float sAs[64], sAd[64];

    const int rel = blockIdx.y;
    const int n0  = blockIdx.x * 128;
    const int tid = threadIdx.x;
    const int wid = tid >> 5, lane = tid & 31, g = lane >> 2, t = lane & 3;

    if (tid < 64) { sAs[tid] = att_src[rel * 64 + tid]; sAd[tid] = att_dst[rel * 64 + tid]; }

    for (int i = tid; i < 1024; i += 256) {
        int row = i >> 3, c16 = (i & 7) * 16;
        int n = n0 + row;
        uint4 vh = make_uint4(0, 0, 0, 0), vl = vh;
        if (n < N_NODES) {
            vh = *(const uint4*)((const char*)g_EH + (size_t)n * 128 + c16);
            vl = *(const uint4*)((const char*)g_EL + (size_t)n * 128 + c16);
        }
        *(uint4*)((char*)Ah + row * 144 + c16) = vh;
        *(uint4*)((char*)Al + row * 144 + c16) = vl;
    }
    for (int i = tid; i < 512; i += 256) {
        int row = i >> 3, c16 = (i & 7) * 16;
        *(uint4*)((char*)Bh + row * 144 + c16) =
            *(const uint4*)((const char*)g_WH + (size_t)rel * 8192 + row * 128 + c16);
        *(uint4*)((char*)Bl + row * 144 + c16) =
            *(const uint4*)((const char*)g_WL + (size_t)rel * 8192 + row * 128 + c16);
    }
    __syncthreads();

    float acc[8][4];
#pragma unroll
    for (int nt = 0; nt < 8; ++nt)
#pragma unroll
        for (int q = 0; q < 4; ++q) acc[nt][q] = 0.f;

    warp_mma_3term(Ah, Al, Bh, Bl, wid * 16, g, t, acc);
    __syncthreads();

    acc_to_stage(stage, acc, wid * 16, g, t);
    __syncthreads();

    {
        const int row = tid >> 1, half = tid & 1;
        float ss = 0.f, sd = 0.f;
#pragma unroll 8
        for (int c = 0; c < 32; ++c) {
            float v = stage[row * PAD + half * 32 + c];
            ss += v * sAs[half * 32 + c];
            sd += v * sAd[half * 32 + c];
        }
        ss += __shfl_xor_sync(0xffffffffu, ss, 1);
        sd += __shfl_xor_sync(0xffffffffu, sd, 1);
        if (half == 0) {
            int n = n0 + row;
            if (n < N_NODES) {
                g_Ssrc[rel * N_NODES + n] = ss;
                g_Sdst[rel * N_NODES + n] = sd;
                g_DEN [rel * N_NODES + n] = __expf(lrelu(ss + sd));  // wself seed
            }
        }
    }
    __syncthreads();

    for (int i = tid; i < 2048; i += 256) {
        int row = i >> 4, q = i & 15;
        int nn = n0 + row;
        if (nn < N_NODES)
            *(float4*)&g_H[((size_t)rel * N_NODES + nn) * 64 + q * 4] =
                *(float4*)&stage[row * PAD + q * 4];
    }
}

// ---------------- final_acc ----------------
__global__ __launch_bounds__(256) void final_acc(
    const float* __restrict__ emb, const float* __restrict__ bias,
    const int* __restrict__ nodes)
{
    extern __shared__ char sm[];
    __nv_bfloat16* Ah = (__nv_bfloat16*)sm;
    __nv_bfloat16* Al = Ah + 128 * ASTR;
    __nv_bfloat16* Bh = Al + 128 * ASTR;
    __nv_bfloat16* Bl = Bh + 64 * ASTR;
    float* stage = (float*)sm;
    __shared__ float sInv[128];
    __shared__ int   sNd[128];

    const int chunk = blockIdx.y;
    const int seg0  = chunk * 8;
    const int seg1  = (seg0 + 8 < N_REL + 1) ? seg0 + 8 : N_REL + 1;
    const int n0  = blockIdx.x * 128;
    const int tid = threadIdx.x;
    const int wid = tid >> 5, lane = tid & 31, g = lane >> 2, t = lane & 3;

    if (tid < 128) {
        int nn = n0 + tid;
        sNd[tid] = (nn < N_NODES) ? nodes[nn] : -1;
    }

    float acc[8][4];
#pragma unroll
    for (int nt = 0; nt < 8; ++nt)
#pragma unroll
        for (int q = 0; q < 4; ++q) acc[nt][q] = 0.f;

    for (int seg = seg0; seg < seg1; ++seg) {
        __syncthreads();
        for (int i = tid; i < 512; i += 256) {
            int row = i >> 3, c16 = (i & 7) * 16;
            *(uint4*)((char*)Bh + row * 144 + c16) =
                *(const uint4*)((const char*)g_W1H + (size_t)seg * 8192 + row * 128 + c16);
            *(uint4*)((char*)Bl + row * 144 + c16) =
                *(const uint4*)((const char*)g_W1L + (size_t)seg * 8192 + row * 128 + c16);
        }
        if (seg > 0 && tid < 128) {
            int nd = sNd[tid];
            sInv[tid] = (nd >= 0) ? (1.f / g_DEN[(seg - 1) * N_NODES + nd]) : 0.f;
        }
        __syncthreads();

        for (int i = tid; i < 2048; i += 256) {
            int row = i >> 4, k4 = (i & 15) * 4;
            int nd = sNd[row];
            float4 v = make_float4(0.f, 0.f, 0.f, 0.f);
            if (nd >= 0) {
                if (seg == 0) {
                    v = *(const float4*)&emb[(size_t)nd * 64 + k4];
                } else {
                    const int r = seg - 1;
                    float4 o  = *(const float4*)&g_OUT[((size_t)r * N_NODES + nd) * 64 + k4];
                    float4 bv = *(const float4*)&bias[r * 64 + k4];
                    float inv = sInv[row];
                    v.x = o.x * inv + bv.x; v.y = o.y * inv + bv.y;
                    v.z = o.z * inv + bv.z; v.w = o.w * inv + bv.w;
                }
            }
            __nv_bfloat16 h0, l0, h1, l1, h2, l2, h3, l3;
            split1(v.x, h0, l0); split1(v.y, h1, l1);
            split1(v.z, h2, l2); split1(v.w, h3, l3);
            *(uint2*)((char*)Ah + row * 144 + k4 * 2) = make_uint2(pk(h0, h1), pk(h2, h3));
            *(uint2*)((char*)Al + row * 144 + k4 * 2) = make_uint2(pk(l0, l1), pk(l2, l3));
        }
        __syncthreads();

        warp_mma_3term(Ah, Al, Bh, Bl, wid * 16, g, t, acc);
    }
    __syncthreads();

    acc_to_stage(stage, acc, wid * 16, g, t);
    __syncthreads();

    float* prep = g_PREP[chunk];
    for (int i = tid; i < 2048; i += 256) {
        int row = i >> 4, q = i & 15;
        int nn = n0 + row;
        if (nn < N_NODES)
            *(float4*)&prep[(size_t)nn * 64 + q * 4] = *(float4*)&stage[row * PAD + q * 4];
    }
}

// ---------------- final_finish ----------------
__global__ __launch_bounds__(256) void final_finish(
    const float* __restrict__ b1, const float* __restrict__ b2, float* __restrict__ out)
{
    extern __shared__ char sm[];
    __nv_bfloat16* Ah = (__nv_bfloat16*)sm;
    __nv_bfloat16* Al = Ah + 128 * ASTR;
    __nv_bfloat16* Bh = Al + 128 * ASTR;
    __nv_bfloat16* Bl = Bh + 64 * ASTR;
    float* stage = (float*)sm;

    const int n0  = blockIdx.x * 128;
    const int tid = threadIdx.x;
    const int wid = tid >> 5, lane = tid & 31, g = lane >> 2, t = lane & 3;

    for (int i = tid; i < 512; i += 256) {
        int row = i >> 3, c16 = (i & 7) * 16;
        *(uint4*)((char*)Bh + row * 144 + c16) =
            *(const uint4*)((const char*)g_W2H + row * 128 + c16);
        *(uint4*)((char*)Bl + row * 144 + c16) =
            *(const uint4*)((const char*)g_W2L + row * 128 + c16);
    }

    for (int i = tid; i < 2048; i += 256) {
        int row = i >> 4, k4 = (i & 15) * 4;
        int nn = n0 + row;
        float4 v = make_float4(0.f, 0.f, 0.f, 0.f);
        if (nn < N_NODES) {
            size_t off = (size_t)nn * 64 + k4;
#pragma unroll
            for (int c = 0; c < N_CHUNK; ++c) {
                float4 p = *(const float4*)&g_PREP[c][off];
                v.x += p.x; v.y += p.y; v.z += p.z; v.w += p.w;
            }
            float4 bb = *(const float4*)&b1[k4];
            v.x = tanhf(v.x + bb.x); v.y = tanhf(v.y + bb.y);
            v.z = tanhf(v.z + bb.z); v.w = tanhf(v.w + bb.w);
        }
        __nv_bfloat16 h0, l0, h1, l1, h2, l2, h3, l3;
        split1(v.x, h0, l0); split1(v.y, h1, l1);
        split1(v.z, h2, l2); split1(v.w, h3, l3);
        *(uint2*)((char*)Ah + row * 144 + k4 * 2) = make_uint2(pk(h0, h1), pk(h2, h3));
        *(uint2*)((char*)Al + row * 144 + k4 * 2) = make_uint2(pk(l0, l1), pk(l2, l3));
    }
    __syncthreads();

    float acc[8][4];
#pragma unroll
    for (int nt = 0; nt < 8; ++nt)
#pragma unroll
        for (int q = 0; q < 4; ++q) acc[nt][q] = 0.f;

    warp_mma_3term(Ah, Al, Bh, Bl, wid * 16, g, t, acc);
    __syncthreads();

    acc_to_stage(stage, acc, wid * 16, g, t);
    __syncthreads();

    for (int i = tid; i < 2048; i += 256) {
        int row = i >> 4, q = i & 15;
        int nn = n0 + row;
        if (nn < N_NODES) {
            float4 v  = *(float4*)&stage[row * PAD + q * 4];
            float4 bb = *(const float4*)&b2[q * 4];
            *(float4*)&out[(size_t)nn * 64 + q * 4] =
                make_float4(v.x + bb.x, v.y + bb.y, v.z + bb.z, v.w + bb.w);
        }
    }
}

// ---------------- launch ----------------
extern "C" void kernel_launch(void* const* d_in, const int* in_sizes, int n_in,
                              void* d_out, int out_size) {
    const float* emb     = (const float*)d_in[0];
    const float* W       = (const float*)d_in[1];
    const float* att_src = (const float*)d_in[2];
    const float* att_dst = (const float*)d_in[3];
    const float* bias    = (const float*)d_in[4];
    const float* W1      = (const float*)d_in[5];
    const float* b1      = (const float*)d_in[6];
    const float* W2      = (const float*)d_in[7];
    const float* b2      = (const float*)d_in[8];
    const int*   edges   = (const int*)d_in[9];
    const int*   nodes   = (const int*)d_in[10];
    float*       out     = (float*)d_out;

    const int MMA_SMEM = (128 * ASTR + 128 * ASTR + 64 * ASTR + 64 * ASTR) * 2;  // 55296
    cudaFuncSetAttribute(gemm_mma,     cudaFuncAttributeMaxDynamicSharedMemorySize, MMA_SMEM);
    cudaFuncSetAttribute(final_acc,    cudaFuncAttributeMaxDynamicSharedMemorySize, MMA_SMEM);
    cudaFuncSetAttribute(final_finish, cudaFuncAttributeMaxDynamicSharedMemorySize, MMA_SMEM);

    csr_zero<<<(N_REL * N_NODES + 255) / 256, 256>>>();
    prep_emb<<<(N_NODES * HID / 2 + 255) / 256, 256>>>(emb);
    prep_w  <<<(N_REL * 4096 + 255) / 256, 256>>>(W);
    prep_w1 <<<((N_REL + 1) * 4096 + 255) / 256, 256>>>(W1);
    prep_w2 <<<(4096 + 255) / 256, 256>>>(W2);

    dim3 ge((N_EDGE + 255) / 256, N_REL);
    csr_count<<<ge, 256>>>(edges);

    const int nb = (N_NODES + 127) / 128;   // 235
    dim3 gg(nb, N_REL);
    gemm_mma<<<gg, 256, MMA_SMEM>>>(att_src, att_dst);

    csr_scan<<<N_REL, 1024>>>();
    csr_fill<<<ge, 256>>>(edges);

    dim3 gn((N_NODES + 15) / 16, N_REL);
    gather_kernel<<<gn, 256>>>();

    dim3 gacc(nb, N_CHUNK);
    final_acc<<<gacc, 256, MMA_SMEM>>>(emb, bias, nodes);
    final_finish<<<nb, 256, MMA_SMEM>>>(b1, b2, out);
}